// round 2
// baseline (speedup 1.0000x reference)
#include <cuda_runtime.h>

#define NBATCH 32
#define CIN    18
#define HH     256
#define WW     256
#define OC     64
#define TLW    64      // tile width
#define TLH    32      // tile height
#define OCB    8       // oc per CTA
#define CCH    2       // channels per staged chunk
#define NCHUNK (CIN / CCH)   // 9
#define INW    66      // TLW + 2 halo
#define INH    34      // TLH + 2 halo

typedef unsigned long long ull;

__device__ __forceinline__ ull pack2(float lo, float hi) {
    ull r; asm("mov.b64 %0, {%1, %2};" : "=l"(r) : "f"(lo), "f"(hi)); return r;
}
__device__ __forceinline__ float2 unpack2(ull v) {
    float2 f; asm("mov.b64 {%0, %1}, %2;" : "=f"(f.x), "=f"(f.y) : "l"(v)); return f;
}
__device__ __forceinline__ ull fma2(ull a, ull b, ull c) {
    ull d; asm("fma.rn.f32x2 %0, %1, %2, %3;" : "=l"(d) : "l"(a), "l"(b), "l"(c)); return d;
}
__device__ __forceinline__ unsigned smem_u32(const void* p) {
    unsigned a;
    asm("{ .reg .u64 t; cvta.to.shared.u64 t, %1; cvt.u32.u64 %0, t; }" : "=r"(a) : "l"(p));
    return a;
}
__device__ __forceinline__ void cp_async4(unsigned saddr, const float* g, bool inb) {
    int sz = inb ? 4 : 0;
    asm volatile("cp.async.ca.shared.global [%0], [%1], 4, %2;"
                 :: "r"(saddr), "l"(g), "r"(sz));
}

__global__ __launch_bounds__(256, 2)
void conv3x3_f32x2_v2(const float* __restrict__ x,
                      const float* __restrict__ wgt,
                      const float* __restrict__ bias,
                      float* __restrict__ out) {
    __shared__ float sIn[2][CCH][INH][INW];     // 35904 B, double-buffered
    __shared__ ull   sW[CIN * 9][OCB];          // 10368 B

    const int tid     = threadIdx.x;
    const int tileX   = (blockIdx.x & 3) * TLW;         // 4 x-tiles
    const int tileY   = (blockIdx.x >> 2) * TLH;        // 8 y-tiles
    const int oc_base = blockIdx.y * OCB;
    const int n       = blockIdx.z;

    // x-fastest lane map: warp covers 4 rows x 8 x-threads -> coalesced stores
    const int xt = tid & 7;        // x-thread: 8 px each
    const int y  = tid >> 3;       // row 0..31
    const int X0 = xt * 8;         // tile-x of first out px (even)

    // Weights, duplicated into both f32x2 halves.
    for (int e = tid; e < CIN * 9 * OCB; e += 256) {
        int k_all = e >> 3;
        int oc    = e & 7;
        float w   = wgt[(oc_base + oc) * (CIN * 9) + k_all];
        sW[k_all][oc] = pack2(w, w);
    }

    // Stage chunk 0 into buffer 0.
    const int CSZ = CCH * INH * INW;   // 4488
    {
        for (int e = tid; e < CSZ; e += 256) {
            int c   = e / (INH * INW);
            int rem = e - c * (INH * INW);
            int yy  = rem / INW;
            int xx  = rem - yy * INW;
            int gy  = tileY + yy - 1;
            int gx  = tileX + xx - 1;
            bool inb = ((unsigned)gy < HH) & ((unsigned)gx < WW);
            const float* g = x + (((long)(n * CIN + c) * HH + gy) * WW + gx);
            cp_async4(smem_u32(&sIn[0][c][yy][xx]), g, inb);
        }
        asm volatile("cp.async.commit_group;");
        asm volatile("cp.async.wait_group 0;");
    }
    __syncthreads();

    ull acc[4][OCB];
    #pragma unroll
    for (int oc = 0; oc < OCB; oc++) {
        float b = bias[oc_base + oc];
        ull bb = pack2(b, b);
        #pragma unroll
        for (int p = 0; p < 4; p++) acc[p][oc] = bb;
    }

    #pragma unroll 1
    for (int k = 0; k < NCHUNK; k++) {
        const int par = k & 1;
        // Prefetch next chunk into the other buffer (overlaps with compute).
        if (k + 1 < NCHUNK) {
            int cc = (k + 1) * CCH;
            for (int e = tid; e < CSZ; e += 256) {
                int c   = e / (INH * INW);
                int rem = e - c * (INH * INW);
                int yy  = rem / INW;
                int xx  = rem - yy * INW;
                int gy  = tileY + yy - 1;
                int gx  = tileX + xx - 1;
                bool inb = ((unsigned)gy < HH) & ((unsigned)gx < WW);
                const float* g = x + (((long)(n * CIN + cc + c) * HH + gy) * WW + gx);
                cp_async4(smem_u32(&sIn[par ^ 1][c][yy][xx]), g, inb);
            }
        }

        // Compute on current buffer.
        #pragma unroll
        for (int c = 0; c < CCH; c++) {
            const int cg = k * CCH + c;     // global channel
            #pragma unroll
            for (int ky = 0; ky < 3; ky++) {
                const ull* row = reinterpret_cast<const ull*>(&sIn[par][c][y + ky][X0]);
                ull e0 = row[0], e1 = row[1], e2 = row[2], e3 = row[3], e4 = row[4];
                float2 f0 = unpack2(e0), f1 = unpack2(e1), f2 = unpack2(e2),
                       f3 = unpack2(e3), f4 = unpack2(e4);
                ull o0 = pack2(f0.y, f1.x);
                ull o1 = pack2(f1.y, f2.x);
                ull o2 = pack2(f2.y, f3.x);
                ull o3 = pack2(f3.y, f4.x);
                const ull* w0r = sW[cg * 9 + ky * 3 + 0];
                const ull* w1r = sW[cg * 9 + ky * 3 + 1];
                const ull* w2r = sW[cg * 9 + ky * 3 + 2];
                #pragma unroll
                for (int oc = 0; oc < OCB; oc++) {
                    ull w0 = w0r[oc], w1 = w1r[oc], w2 = w2r[oc];
                    acc[0][oc] = fma2(e0, w0, fma2(o0, w1, fma2(e1, w2, acc[0][oc])));
                    acc[1][oc] = fma2(e1, w0, fma2(o1, w1, fma2(e2, w2, acc[1][oc])));
                    acc[2][oc] = fma2(e2, w0, fma2(o2, w1, fma2(e3, w2, acc[2][oc])));
                    acc[3][oc] = fma2(e3, w0, fma2(o3, w1, fma2(e4, w2, acc[3][oc])));
                }
            }
        }

        asm volatile("cp.async.commit_group;");
        asm volatile("cp.async.wait_group 0;");
        __syncthreads();
    }

    // Write 8 px x 8 oc as float2 pairs (X0 even -> 8B aligned; lanes coalesce 64B).
    const long gy = tileY + y;
    const long gx = tileX + X0;
    #pragma unroll
    for (int oc = 0; oc < OCB; oc++) {
        float* p = out + ((((long)n * OC + oc_base + oc) * HH + gy) * WW + gx);
        #pragma unroll
        for (int q = 0; q < 4; q++) {
            float2 v = unpack2(acc[q][oc]);
            reinterpret_cast<float2*>(p)[q] = v;
        }
    }
}

extern "C" void kernel_launch(void* const* d_in, const int* in_sizes, int n_in,
                              void* d_out, int out_size) {
    const float* x    = (const float*)d_in[0];
    const float* wgt  = (const float*)d_in[1];
    const float* bias = (const float*)d_in[2];
    float* out        = (float*)d_out;

    dim3 grid(32 /* 4x8 tiles */, OC / OCB /* 8 */, NBATCH /* 32 */);
    conv3x3_f32x2_v2<<<grid, 256>>>(x, wgt, bias, out);
}

// round 3
// speedup vs baseline: 1.4164x; 1.4164x over previous
#include <cuda_runtime.h>

#define CIN 18
#define HH  256
#define WW  256
#define OC  64
#define OCB 8
#define TLW 64
#define TLH 32

typedef unsigned long long ull;

__device__ __forceinline__ ull pack2(float lo, float hi) {
    ull r; asm("mov.b64 %0, {%1, %2};" : "=l"(r) : "f"(lo), "f"(hi)); return r;
}
__device__ __forceinline__ float2 unpack2(ull v) {
    float2 f; asm("mov.b64 {%0, %1}, %2;" : "=f"(f.x), "=f"(f.y) : "l"(v)); return f;
}
__device__ __forceinline__ ull fma2(ull a, ull b, ull c) {
    ull d; asm("fma.rn.f32x2 %0, %1, %2, %3;" : "=l"(d) : "l"(a), "l"(b), "l"(c)); return d;
}

__global__ __launch_bounds__(256, 2)
void conv3x3_v3(const float* __restrict__ x,
                const float* __restrict__ wgt,
                const float* __restrict__ bias,
                float* __restrict__ out) {
    __shared__ ull sW[CIN * 9][OCB];   // 10368 B, weights duplicated in both f32x2 halves

    const int tid     = threadIdx.x;
    const int oc_base = blockIdx.x * OCB;           // oc-block fastest: input reuse in L2
    const int tile    = blockIdx.y;                 // 0..31 (4 x-tiles * 8 y-tiles)
    const int n       = blockIdx.z;
    const int tileX   = (tile & 3) * TLW;
    const int tileY   = (tile >> 2) * TLH;

    for (int e = tid; e < CIN * 9 * OCB; e += 256) {
        int k  = e >> 3;
        int oc = e & 7;
        float w = wgt[(oc_base + oc) * (CIN * 9) + k];
        sW[k][oc] = pack2(w, w);
    }

    const int xt  = tid & 7;          // 8 x-threads, 8 px each
    const int yy  = tid >> 3;         // 32 rows
    const int gx0 = tileX + xt * 8;   // even -> 8B/16B aligned accesses
    const int gy  = tileY + yy;

    const bool leftOK  = gx0 > 0;
    const bool rightOK = gx0 < 248;
    const bool rOK0    = gy > 0;
    const bool rOK2    = gy < (HH - 1);

    ull acc[4][OCB];
    #pragma unroll
    for (int oc = 0; oc < OCB; oc++) {
        float b = bias[oc_base + oc];
        ull bb = pack2(b, b);
        #pragma unroll
        for (int q = 0; q < 4; q++) acc[q][oc] = bb;
    }

    __syncthreads();   // weights ready; only barrier in the kernel

    const float* xbase = x + (((long)n * CIN * HH + gy) * WW) + gx0;

    #pragma unroll 1
    for (int c = 0; c < CIN; c++) {
        const float* rb    = xbase + (long)c * (HH * WW);
        const ull*   wbase = &sW[c * 9][0];
        #pragma unroll
        for (int ky = 0; ky < 3; ky++) {
            const float* r  = rb + (ky - 1) * WW;
            const bool   rv = (ky == 0) ? rOK0 : (ky == 2) ? rOK2 : true;

            ull e0 = 0, e1 = 0, e2 = 0, e3 = 0;
            float L = 0.0f, R = 0.0f;
            if (rv) {
                e0 = *(const ull*)(r);
                e1 = *(const ull*)(r + 2);
                e2 = *(const ull*)(r + 4);
                e3 = *(const ull*)(r + 6);
                if (leftOK)  L = r[-1];
                if (rightOK) R = r[8];
            }
            float2 f0 = unpack2(e0), f1 = unpack2(e1), f2 = unpack2(e2), f3 = unpack2(e3);
            ull om = pack2(L,    f0.x);
            ull o0 = pack2(f0.y, f1.x);
            ull o1 = pack2(f1.y, f2.x);
            ull o2 = pack2(f2.y, f3.x);
            ull o3 = pack2(f3.y, R);

            const ull* w0r = wbase + (ky * 3 + 0) * OCB;
            const ull* w1r = wbase + (ky * 3 + 1) * OCB;
            const ull* w2r = wbase + (ky * 3 + 2) * OCB;
            #pragma unroll
            for (int oc = 0; oc < OCB; oc++) {
                ull w0 = w0r[oc], w1 = w1r[oc], w2 = w2r[oc];
                acc[0][oc] = fma2(om, w0, fma2(e0, w1, fma2(o0, w2, acc[0][oc])));
                acc[1][oc] = fma2(o0, w0, fma2(e1, w1, fma2(o1, w2, acc[1][oc])));
                acc[2][oc] = fma2(o1, w0, fma2(e2, w1, fma2(o2, w2, acc[2][oc])));
                acc[3][oc] = fma2(o2, w0, fma2(e3, w1, fma2(o3, w2, acc[3][oc])));
            }
        }
    }

    // 8 oc x 8 px, written as two float4 per oc (gx0*4 is 32B-aligned).
    float* op = out + (((long)n * OC + oc_base) * HH + gy) * WW + gx0;
    #pragma unroll
    for (int oc = 0; oc < OCB; oc++) {
        float2 a0 = unpack2(acc[0][oc]);
        float2 a1 = unpack2(acc[1][oc]);
        float2 a2 = unpack2(acc[2][oc]);
        float2 a3 = unpack2(acc[3][oc]);
        float4 v0 = make_float4(a0.x, a0.y, a1.x, a1.y);
        float4 v1 = make_float4(a2.x, a2.y, a3.x, a3.y);
        *(float4*)(op)     = v0;
        *(float4*)(op + 4) = v1;
        op += (long)HH * WW;
    }
}

extern "C" void kernel_launch(void* const* d_in, const int* in_sizes, int n_in,
                              void* d_out, int out_size) {
    const float* x    = (const float*)d_in[0];
    const float* wgt  = (const float*)d_in[1];
    const float* bias = (const float*)d_in[2];
    float* out        = (float*)d_out;

    dim3 grid(OC / OCB /* 8 */, 32 /* 4x8 tiles */, 32 /* batch */);
    conv3x3_v3<<<grid, 256>>>(x, wgt, bias, out);
}

// round 5
// speedup vs baseline: 2.5540x; 1.8032x over previous
#include <cuda_runtime.h>
#include <cuda_fp16.h>
#include <cstdint>

#define CIN 18
#define HH  256
#define WW  256
#define OCN 64
#define HWX (HH * WW)
#define NCHUNK 9

#define SMEM_A 0
#define SMEM_B 16384
#define SMEM_TOTAL (16384 + NCHUNK * 8192)   // 90112 B

#define SW(o) ((o) ^ (((o) >> 3) & 0x70))

__device__ __forceinline__ uint32_t smem_u32(const void* p) {
    uint32_t a;
    asm("{ .reg .u64 t; cvta.to.shared.u64 t, %1; cvt.u32.u64 %0, t; }" : "=r"(a) : "l"(p));
    return a;
}
__device__ __forceinline__ void sts128(uint4 v, uint32_t addr) {
    asm volatile("st.shared.v4.b32 [%0], {%1, %2, %3, %4};"
                 :: "r"(addr), "r"(v.x), "r"(v.y), "r"(v.z), "r"(v.w) : "memory");
}
__device__ __forceinline__ uint32_t lds32(uint32_t addr) {
    uint32_t v;
    asm volatile("ld.shared.b32 %0, [%1];" : "=r"(v) : "r"(addr));
    return v;
}
__device__ __forceinline__ void ldmatrix_x4(uint32_t* r, uint32_t addr) {
    asm volatile("ldmatrix.sync.aligned.m8n8.x4.shared.b16 {%0, %1, %2, %3}, [%4];"
                 : "=r"(r[0]), "=r"(r[1]), "=r"(r[2]), "=r"(r[3]) : "r"(addr));
}
__device__ __forceinline__ void mma16816(float* d, const uint32_t* a, const uint32_t* b) {
    asm volatile("mma.sync.aligned.m16n8k16.row.col.f32.f16.f16.f32 "
                 "{%0, %1, %2, %3}, {%4, %5, %6, %7}, {%8, %9}, {%0, %1, %2, %3};"
                 : "+f"(d[0]), "+f"(d[1]), "+f"(d[2]), "+f"(d[3])
                 : "r"(a[0]), "r"(a[1]), "r"(a[2]), "r"(a[3]), "r"(b[0]), "r"(b[1]));
}

__global__ __launch_bounds__(256, 2)
void conv3x3_hmma(const float* __restrict__ x,
                  const float* __restrict__ wgt,
                  const float* __restrict__ bias,
                  float* __restrict__ out) {
    extern __shared__ char smem[];
    const uint32_t sb  = smem_u32(smem);
    const int tid  = threadIdx.x;
    const int wid  = tid >> 5;
    const int lane = tid & 31;

    // ---- Build B (weights, fp16 hi/lo split) once per CTA: 9 chunks x 64 oc x 64 K-cols ----
    // K-col layout per channel (32 cols): tap t -> cols {3t,3t+1,3t+2} = (w_hi, w_hi, w_lo); 27..31 zero.
    for (int i = tid; i < NCHUNK * 64; i += 256) {
        int chunk = i >> 6, oc = i & 63;
        __align__(16) __half cols[64];
        #pragma unroll
        for (int q = 0; q < 64; q++) cols[q] = __ushort_as_half(0);
        #pragma unroll
        for (int cl = 0; cl < 2; cl++) {
            int c = chunk * 2 + cl;
            #pragma unroll
            for (int t = 0; t < 9; t++) {
                float w  = wgt[oc * (CIN * 9) + c * 9 + t];
                __half h = __float2half_rn(w);
                __half l = __float2half_rn(w - __half2float(h));
                cols[cl * 32 + t * 3 + 0] = h;
                cols[cl * 32 + t * 3 + 1] = h;
                cols[cl * 32 + t * 3 + 2] = l;
            }
        }
        const uint4* src = reinterpret_cast<const uint4*>(cols);
        #pragma unroll
        for (int q = 0; q < 8; q++) {
            uint32_t off = (uint32_t)oc * 128 + q * 16;
            sts128(src[q], sb + SMEM_B + chunk * 8192 + SW(off));
        }
    }

    // Warp tiling: 4 (M) x 2 (N); warp tile 32 px x 32 oc.
    const int wm = wid & 3;
    const int wn = wid >> 2;

    // Bias cached per thread: oc0 = wn*32 + nt*8 + (lane&3)*2 + {0,1}
    float bv[4][2];
    #pragma unroll
    for (int nt = 0; nt < 4; nt++) {
        int oc0 = wn * 32 + nt * 8 + (lane & 3) * 2;
        bv[nt][0] = bias[oc0];
        bv[nt][1] = bias[oc0 + 1];
    }

    // A-build role: thread -> (pixel px, channel-half cl)
    const int px = tid & 127;
    const int cl = tid >> 7;

    #pragma unroll 1
    for (int si = 0; si < 16; si++) {
        const int s  = blockIdx.x * 16 + si;
        const int n  = s >> 9;
        const int y  = (s >> 1) & 255;
        const int x0 = (s & 1) << 7;
        const int gx = x0 + px;          // center x of this thread's pixel

        float acc[2][4][4];
        #pragma unroll
        for (int mt = 0; mt < 2; mt++)
            #pragma unroll
            for (int nt = 0; nt < 4; nt++)
                #pragma unroll
                for (int q = 0; q < 4; q++) acc[mt][nt][q] = 0.0f;

        // Prefetch chunk 0 input taps.
        float v[9];
        {
            const int c = cl;
            const float* base = x + ((long)(n * CIN + c) * HH) * WW;
            #pragma unroll
            for (int ky = 0; ky < 3; ky++) {
                int ry = y + ky - 1;
                bool rv = (unsigned)ry < HH;
                const float* r = base + (long)ry * WW + gx - 1;
                #pragma unroll
                for (int kx = 0; kx < 3; kx++) {
                    int gxx = gx + kx - 1;
                    bool ok = rv && ((unsigned)gxx < WW);
                    v[ky * 3 + kx] = ok ? r[kx] : 0.0f;
                }
            }
        }

        #pragma unroll 1
        for (int k = 0; k < NCHUNK; k++) {
            __syncthreads();   // previous chunk's smem A reads complete (ldmatrix is warp-sync)

            // Convert prefetched taps -> fp16 hi/lo, store A row segment (swizzled).
            {
                __align__(16) __half a[32];
                #pragma unroll
                for (int t = 0; t < 9; t++) {
                    float f  = v[t];
                    __half h = __float2half_rn(f);
                    __half l = __float2half_rn(f - __half2float(h));
                    a[t * 3 + 0] = h;
                    a[t * 3 + 1] = l;
                    a[t * 3 + 2] = h;
                }
                #pragma unroll
                for (int q = 27; q < 32; q++) a[q] = __ushort_as_half(0);
                const uint4* src = reinterpret_cast<const uint4*>(a);
                uint32_t rowoff = (uint32_t)px * 128 + cl * 64;
                #pragma unroll
                for (int q = 0; q < 4; q++)
                    sts128(src[q], sb + SMEM_A + SW(rowoff + q * 16));
            }
            __syncthreads();

            // Prefetch next chunk's taps (LDG in flight during MMAs below).
            if (k + 1 < NCHUNK) {
                const int c = (k + 1) * 2 + cl;
                const float* base = x + ((long)(n * CIN + c) * HH) * WW;
                #pragma unroll
                for (int ky = 0; ky < 3; ky++) {
                    int ry = y + ky - 1;
                    bool rv = (unsigned)ry < HH;
                    const float* r = base + (long)ry * WW + gx - 1;
                    #pragma unroll
                    for (int kx = 0; kx < 3; kx++) {
                        int gxx = gx + kx - 1;
                        bool ok = rv && ((unsigned)gxx < WW);
                        v[ky * 3 + kx] = ok ? r[kx] : 0.0f;
                    }
                }
            }

            // MMA over this chunk's 64 K-cols (4 k16 steps).
            const uint32_t bbase = sb + SMEM_B + k * 8192;
            #pragma unroll
            for (int st = 0; st < 4; st++) {
                uint32_t afr[2][4];
                {
                    const int r    = lane & 7;
                    const int tsel = lane >> 3;
                    const int kb   = st * 32 + (tsel >> 1) * 16;
                    #pragma unroll
                    for (int mt = 0; mt < 2; mt++) {
                        int row = wm * 32 + mt * 16 + (tsel & 1) * 8 + r;
                        uint32_t off = (uint32_t)row * 128 + kb;
                        ldmatrix_x4(afr[mt], sb + SMEM_A + SW(off));
                    }
                }
                uint32_t bfr[4][2];
                #pragma unroll
                for (int nt = 0; nt < 4; nt++) {
                    int nrow = wn * 32 + nt * 8 + (lane >> 2);
                    uint32_t off = (uint32_t)nrow * 128 + st * 32 + (lane & 3) * 4;
                    bfr[nt][0] = lds32(bbase + SW(off));
                    bfr[nt][1] = lds32(bbase + SW(off + 16));
                }
                #pragma unroll
                for (int mt = 0; mt < 2; mt++)
                    #pragma unroll
                    for (int nt = 0; nt < 4; nt++)
                        mma16816(acc[mt][nt], afr[mt], bfr[nt]);
            }
        }

        // ---- Epilogue: bias + store ----
        float* outn = out + (long)n * OCN * HWX + (long)y * WW + x0;
        #pragma unroll
        for (int mt = 0; mt < 2; mt++) {
            int px0 = wm * 32 + mt * 16 + (lane >> 2);
            #pragma unroll
            for (int nt = 0; nt < 4; nt++) {
                int oc0 = wn * 32 + nt * 8 + (lane & 3) * 2;
                float* p = outn + (long)oc0 * HWX + px0;
                p[0]       = acc[mt][nt][0] + bv[nt][0];
                p[HWX]     = acc[mt][nt][1] + bv[nt][1];
                p[8]       = acc[mt][nt][2] + bv[nt][0];
                p[HWX + 8] = acc[mt][nt][3] + bv[nt][1];
            }
        }
    }
}

extern "C" void kernel_launch(void* const* d_in, const int* in_sizes, int n_in,
                              void* d_out, int out_size) {
    const float* x    = (const float*)d_in[0];
    const float* wgt  = (const float*)d_in[1];
    const float* bias = (const float*)d_in[2];
    float* out        = (float*)d_out;

    cudaFuncSetAttribute(conv3x3_hmma, cudaFuncAttributeMaxDynamicSharedMemorySize, SMEM_TOTAL);
    conv3x3_hmma<<<1024, 256, SMEM_TOTAL>>>(x, wgt, bias, out);
}

// round 6
// speedup vs baseline: 3.0024x; 1.1756x over previous
#include <cuda_runtime.h>
#include <cuda_fp16.h>
#include <cstdint>

#define CIN 18
#define HH  256
#define WW  256
#define OCN 64
#define HWX (HH * WW)
#define NCHUNK 9

#define SMEM_A0 0
#define SMEM_A1 16384
#define SMEM_B  32768
#define SMEM_TOTAL (32768 + NCHUNK * 8192)   // 106496 B -> 2 CTAs/SM

#define SW(o) ((o) ^ (((o) >> 3) & 0x70))

__device__ __forceinline__ uint32_t smem_u32(const void* p) {
    uint32_t a;
    asm("{ .reg .u64 t; cvta.to.shared.u64 t, %1; cvt.u32.u64 %0, t; }" : "=r"(a) : "l"(p));
    return a;
}
__device__ __forceinline__ void sts128(uint4 v, uint32_t addr) {
    asm volatile("st.shared.v4.b32 [%0], {%1, %2, %3, %4};"
                 :: "r"(addr), "r"(v.x), "r"(v.y), "r"(v.z), "r"(v.w) : "memory");
}
__device__ __forceinline__ void ldmatrix_x4(uint32_t* r, uint32_t addr) {
    asm volatile("ldmatrix.sync.aligned.m8n8.x4.shared.b16 {%0, %1, %2, %3}, [%4];"
                 : "=r"(r[0]), "=r"(r[1]), "=r"(r[2]), "=r"(r[3]) : "r"(addr));
}
__device__ __forceinline__ void mma16816(float* d, const uint32_t* a, const uint32_t* b) {
    asm volatile("mma.sync.aligned.m16n8k16.row.col.f32.f16.f16.f32 "
                 "{%0, %1, %2, %3}, {%4, %5, %6, %7}, {%8, %9}, {%0, %1, %2, %3};"
                 : "+f"(d[0]), "+f"(d[1]), "+f"(d[2]), "+f"(d[3])
                 : "r"(a[0]), "r"(a[1]), "r"(a[2]), "r"(a[3]), "r"(b[0]), "r"(b[1]));
}

__global__ __launch_bounds__(128)
void conv3x3_hmma2(const float* __restrict__ x,
                   const float* __restrict__ wgt,
                   const float* __restrict__ bias,
                   float* __restrict__ out) {
    extern __shared__ char smem[];
    const uint32_t sb   = smem_u32(smem);
    const int tid  = threadIdx.x;
    const int wid  = tid >> 5;
    const int lane = tid & 31;

    // ---- Build B (weights, fp16 hi/lo 3-col split) once per CTA ----
    for (int i = tid; i < NCHUNK * 64; i += 128) {
        int chunk = i >> 6, oc = i & 63;
        __align__(16) __half cols[64];
        #pragma unroll
        for (int q = 0; q < 64; q++) cols[q] = __ushort_as_half(0);
        #pragma unroll
        for (int cl = 0; cl < 2; cl++) {
            int c = chunk * 2 + cl;
            #pragma unroll
            for (int t = 0; t < 9; t++) {
                float w  = wgt[oc * (CIN * 9) + c * 9 + t];
                __half h = __float2half_rn(w);
                __half l = __float2half_rn(w - __half2float(h));
                cols[cl * 32 + t * 3 + 0] = h;
                cols[cl * 32 + t * 3 + 1] = h;
                cols[cl * 32 + t * 3 + 2] = l;
            }
        }
        const uint4* src = reinterpret_cast<const uint4*>(cols);
        #pragma unroll
        for (int q = 0; q < 8; q++) {
            uint32_t off = (uint32_t)oc * 128 + q * 16;
            sts128(src[q], sb + SMEM_B + chunk * 8192 + SW(off));
        }
    }

    // Warp tiling: warp tile 64 px (M) x 32 oc (N). 4 warps = wm2 x wn2.
    const int wm = wid & 1;
    const int wn = wid >> 1;

    float bv[4][2];
    #pragma unroll
    for (int nt = 0; nt < 4; nt++) {
        int oc0 = wn * 32 + nt * 8 + (lane & 3) * 2;
        bv[nt][0] = bias[oc0];
        bv[nt][1] = bias[oc0 + 1];
    }

    // ldmatrix address lanes
    const int tsel = lane >> 3, rr = lane & 7;     // A: 4 groups of 8
    const int bg   = lane >> 3;                    // B: 4 groups of 8

    const int px = tid;   // A-build: this thread owns pixel px (0..127), both channels

    #pragma unroll 1
    for (int si = 0; si < 16; si++) {
        const int s  = blockIdx.x * 16 + si;
        const int n  = s >> 9;
        const int y  = (s >> 1) & 255;
        const int x0 = (s & 1) << 7;
        const int gx = x0 + px;

        __syncthreads();   // previous strip's MMAs done before overwriting A bufs

        // Prefetch chunk-0 taps (channels 0,1).
        float v[2][9];
        #pragma unroll
        for (int cl = 0; cl < 2; cl++) {
            const float* base = x + ((long)(n * CIN + cl) * HH) * WW;
            #pragma unroll
            for (int ky = 0; ky < 3; ky++) {
                int ry = y + ky - 1;
                bool rv = (unsigned)ry < HH;
                const float* r = base + (long)ry * WW + gx - 1;
                #pragma unroll
                for (int kx = 0; kx < 3; kx++) {
                    int gxx = gx + kx - 1;
                    v[cl][ky * 3 + kx] = (rv && (unsigned)gxx < WW) ? r[kx] : 0.0f;
                }
            }
        }

        float acc[4][4][4];
        #pragma unroll
        for (int mt = 0; mt < 4; mt++)
            #pragma unroll
            for (int nt = 0; nt < 4; nt++)
                #pragma unroll
                for (int q = 0; q < 4; q++) acc[mt][nt][q] = 0.0f;

        #pragma unroll 1
        for (int k = 0; k < NCHUNK; k++) {
            const uint32_t abase = sb + ((k & 1) ? SMEM_A1 : SMEM_A0);

            // Build A rows for both channel halves from prefetched taps.
            #pragma unroll
            for (int cl = 0; cl < 2; cl++) {
                __align__(16) __half a[32];
                #pragma unroll
                for (int t = 0; t < 9; t++) {
                    float f  = v[cl][t];
                    __half h = __float2half_rn(f);
                    __half l = __float2half_rn(f - __half2float(h));
                    a[t * 3 + 0] = h;
                    a[t * 3 + 1] = l;
                    a[t * 3 + 2] = h;
                }
                #pragma unroll
                for (int q = 27; q < 32; q++) a[q] = __ushort_as_half(0);
                const uint4* src = reinterpret_cast<const uint4*>(a);
                uint32_t rowoff = (uint32_t)px * 128 + cl * 64;
                #pragma unroll
                for (int q = 0; q < 4; q++)
                    sts128(src[q], abase + SW(rowoff + q * 16));
            }

            // Prefetch next chunk's taps (LDGs in flight through sync + MMA).
            if (k + 1 < NCHUNK) {
                #pragma unroll
                for (int cl = 0; cl < 2; cl++) {
                    const int c = (k + 1) * 2 + cl;
                    const float* base = x + ((long)(n * CIN + c) * HH) * WW;
                    #pragma unroll
                    for (int ky = 0; ky < 3; ky++) {
                        int ry = y + ky - 1;
                        bool rv = (unsigned)ry < HH;
                        const float* r = base + (long)ry * WW + gx - 1;
                        #pragma unroll
                        for (int kx = 0; kx < 3; kx++) {
                            int gxx = gx + kx - 1;
                            v[cl][ky * 3 + kx] = (rv && (unsigned)gxx < WW) ? r[kx] : 0.0f;
                        }
                    }
                }
            }

            __syncthreads();

            // MMA over this chunk: 4 k16 steps, warp tile 64x32.
            const uint32_t bbase = sb + SMEM_B + k * 8192;
            #pragma unroll
            for (int st = 0; st < 4; st++) {
                uint32_t afr[4][4];
                #pragma unroll
                for (int mt = 0; mt < 4; mt++) {
                    int row = wm * 64 + mt * 16 + (tsel & 1) * 8 + rr;
                    uint32_t off = (uint32_t)row * 128 + st * 32 + (tsel >> 1) * 16;
                    ldmatrix_x4(afr[mt], abase + SW(off));
                }
                uint32_t bfr[4][2];
                #pragma unroll
                for (int p = 0; p < 2; p++) {   // nt pairs (2p, 2p+1)
                    int row = wn * 32 + p * 16 + (bg >> 1) * 8 + rr;
                    uint32_t off = (uint32_t)row * 128 + st * 32 + (bg & 1) * 16;
                    uint32_t m[4];
                    ldmatrix_x4(m, bbase + SW(off));
                    bfr[2 * p][0]     = m[0];
                    bfr[2 * p][1]     = m[1];
                    bfr[2 * p + 1][0] = m[2];
                    bfr[2 * p + 1][1] = m[3];
                }
                #pragma unroll
                for (int mt = 0; mt < 4; mt++)
                    #pragma unroll
                    for (int nt = 0; nt < 4; nt++)
                        mma16816(acc[mt][nt], afr[mt], bfr[nt]);
            }
        }

        // ---- Epilogue: bias + store ----
        float* outn = out + (long)n * OCN * HWX + (long)y * WW + x0;
        #pragma unroll
        for (int mt = 0; mt < 4; mt++) {
            int px0 = wm * 64 + mt * 16 + (lane >> 2);
            #pragma unroll
            for (int nt = 0; nt < 4; nt++) {
                int oc0 = wn * 32 + nt * 8 + (lane & 3) * 2;
                float* p = outn + (long)oc0 * HWX + px0;
                p[0]       = acc[mt][nt][0] + bv[nt][0];
                p[HWX]     = acc[mt][nt][1] + bv[nt][1];
                p[8]       = acc[mt][nt][2] + bv[nt][0];
                p[HWX + 8] = acc[mt][nt][3] + bv[nt][1];
            }
        }
    }
}

extern "C" void kernel_launch(void* const* d_in, const int* in_sizes, int n_in,
                              void* d_out, int out_size) {
    const float* x    = (const float*)d_in[0];
    const float* wgt  = (const float*)d_in[1];
    const float* bias = (const float*)d_in[2];
    float* out        = (float*)d_out;

    cudaFuncSetAttribute(conv3x3_hmma2, cudaFuncAttributeMaxDynamicSharedMemorySize, SMEM_TOTAL);
    conv3x3_hmma2<<<1024, 128, SMEM_TOTAL>>>(x, wgt, bias, out);
}